// round 5
// baseline (speedup 1.0000x reference)
#include <cuda_runtime.h>
#include <math.h>
#include <stdint.h>

#define VV 20000
#define HH 512
#define BB 128
#define SS 64
#define TD 32

// ---------------- scratch (device globals) ----------------
__device__ float g_xg[BB * SS * 2048];
__device__ float g_enc_out[BB * SS * HH];
__device__ float g_keys[BB * SS * HH];
__device__ float g_embW[TD * BB * 2048];
__device__ float g_hs[TD * BB * HH];
__device__ float g_h0[BB * HH];
__device__ float g_h1[BB * HH];
__device__ float g_c[BB * HH];
__device__ float g_q[BB * HH];
__device__ float g_ctx[BB * HH];
__device__ int   g_rows[TD * BB];

// ---------------- MUFU-free transcendentals ----------------
__device__ __forceinline__ float exp_fast(float x) {
    x = fminf(fmaxf(x, -87.f), 87.f);
    float y = x * 1.4426950408889634f;
    float fl = floorf(y);
    float f = y - fl;
    float p =              1.3215486790e-6f;
    p = fmaf(p, f, 1.5252733804e-5f);
    p = fmaf(p, f, 1.5403530394e-4f);
    p = fmaf(p, f, 1.3333558146e-3f);
    p = fmaf(p, f, 9.6181291076e-3f);
    p = fmaf(p, f, 5.5504108664e-2f);
    p = fmaf(p, f, 2.4022650696e-1f);
    p = fmaf(p, f, 6.9314718056e-1f);
    p = fmaf(p, f, 1.0f);
    int i = (int)fl;
    return __int_as_float((i + 127) << 23) * p;
}
__device__ __forceinline__ float rcp_fast(float d) {
    float r = __uint_as_float(0x7EF311C3u - __float_as_uint(d));
    r = r * fmaf(-d, r, 2.0f);
    r = r * fmaf(-d, r, 2.0f);
    r = r * fmaf(-d, r, 2.0f);
    return r;
}
__device__ __forceinline__ float sig_fast(float x) {
    return rcp_fast(1.0f + exp_fast(-x));
}
__device__ __forceinline__ float tanh_fast(float x) {
    float a = fabsf(x);
    float t = exp_fast(-2.0f * a);
    float r = (1.0f - t) * rcp_fast(1.0f + t);
    return copysignf(r, x);
}

// ---------------- cp.async helpers ----------------
__device__ __forceinline__ void cpa16(uint32_t dst, const void* src) {
    asm volatile("cp.async.cg.shared.global [%0], [%1], 16;\n" :: "r"(dst), "l"(src));
}
__device__ __forceinline__ void cpcommit() { asm volatile("cp.async.commit_group;\n"); }
template<int N> __device__ __forceinline__ void cpwait() {
    asm volatile("cp.async.wait_group %0;\n" :: "n"(N));
}

// ================= TF32 MMA logits GEMM (validated R4) =================
#define LST 136
__global__ __launch_bounds__(256) void gemm_tf32_logits(
    const float* __restrict__ A, const float* __restrict__ B,
    const float* __restrict__ bias, float* __restrict__ C)
{
    __shared__ float As[2][16][LST];
    __shared__ float Bs[2][16][LST];
    const int bm = blockIdx.y * 128;
    const int bn = blockIdx.x * 128;
    const int tid = threadIdx.x;
    const int warp = tid >> 5, lane = tid & 31;
    const int wm = (warp >> 2) * 64, wn = (warp & 3) * 32;
    const int g = lane >> 2, tg = lane & 3;

    const int lr = tid & 127;
    const int lc = tid >> 7;
    const float* Ap = A + (size_t)(bm + lr) * 512 + lc * 4;
    const int bnr = bn + lr;
    const bool bok = (bnr < VV);
    const float* Bp = B + (size_t)(bok ? bnr : 0) * 512 + lc * 4;

    float acc[4][4][4];
#pragma unroll
    for (int mt = 0; mt < 4; mt++)
#pragma unroll
        for (int nt = 0; nt < 4; nt++)
#pragma unroll
            for (int i = 0; i < 4; i++) acc[mt][nt][i] = 0.f;

    float4 av0 = *(const float4*)(Ap);
    float4 av1 = *(const float4*)(Ap + 8);
    float4 bv0 = bok ? *(const float4*)(Bp)     : make_float4(0.f,0.f,0.f,0.f);
    float4 bv1 = bok ? *(const float4*)(Bp + 8) : make_float4(0.f,0.f,0.f,0.f);

#define STORE_T(buf) do { \
    As[buf][lc*4+0][lr]=av0.x; As[buf][lc*4+1][lr]=av0.y; \
    As[buf][lc*4+2][lr]=av0.z; As[buf][lc*4+3][lr]=av0.w; \
    As[buf][lc*4+8][lr]=av1.x; As[buf][lc*4+9][lr]=av1.y; \
    As[buf][lc*4+10][lr]=av1.z; As[buf][lc*4+11][lr]=av1.w; \
    Bs[buf][lc*4+0][lr]=bv0.x; Bs[buf][lc*4+1][lr]=bv0.y; \
    Bs[buf][lc*4+2][lr]=bv0.z; Bs[buf][lc*4+3][lr]=bv0.w; \
    Bs[buf][lc*4+8][lr]=bv1.x; Bs[buf][lc*4+9][lr]=bv1.y; \
    Bs[buf][lc*4+10][lr]=bv1.z; Bs[buf][lc*4+11][lr]=bv1.w; \
} while(0)

    STORE_T(0);
    __syncthreads();

    for (int kb = 0; kb < 32; kb++) {
        const int cur = kb & 1;
        if (kb < 31) {
            const float* Ap2 = Ap + (kb + 1) * 16;
            const float* Bp2 = Bp + (kb + 1) * 16;
            av0 = *(const float4*)(Ap2);
            av1 = *(const float4*)(Ap2 + 8);
            bv0 = bok ? *(const float4*)(Bp2)     : make_float4(0.f,0.f,0.f,0.f);
            bv1 = bok ? *(const float4*)(Bp2 + 8) : make_float4(0.f,0.f,0.f,0.f);
        }
#pragma unroll
        for (int ks = 0; ks < 2; ks++) {
            const int k = ks * 8;
            unsigned afr[4][4], bfr[4][2];
#pragma unroll
            for (int mt = 0; mt < 4; mt++) {
                const int m = wm + mt * 16 + g;
                afr[mt][0] = __float_as_uint(As[cur][k + tg][m]);
                afr[mt][1] = __float_as_uint(As[cur][k + tg][m + 8]);
                afr[mt][2] = __float_as_uint(As[cur][k + tg + 4][m]);
                afr[mt][3] = __float_as_uint(As[cur][k + tg + 4][m + 8]);
            }
#pragma unroll
            for (int nt = 0; nt < 4; nt++) {
                const int n = wn + nt * 8 + g;
                bfr[nt][0] = __float_as_uint(Bs[cur][k + tg][n]);
                bfr[nt][1] = __float_as_uint(Bs[cur][k + tg + 4][n]);
            }
#pragma unroll
            for (int mt = 0; mt < 4; mt++)
#pragma unroll
                for (int nt = 0; nt < 4; nt++) {
                    asm volatile(
                        "mma.sync.aligned.m16n8k8.row.col.f32.tf32.tf32.f32 "
                        "{%0,%1,%2,%3}, {%4,%5,%6,%7}, {%8,%9}, {%0,%1,%2,%3};"
                        : "+f"(acc[mt][nt][0]), "+f"(acc[mt][nt][1]),
                          "+f"(acc[mt][nt][2]), "+f"(acc[mt][nt][3])
                        : "r"(afr[mt][0]), "r"(afr[mt][1]), "r"(afr[mt][2]), "r"(afr[mt][3]),
                          "r"(bfr[nt][0]), "r"(bfr[nt][1]));
                }
        }
        __syncthreads();
        if (kb < 31) {
            STORE_T(cur ^ 1);
            __syncthreads();
        }
    }

#pragma unroll
    for (int mt = 0; mt < 4; mt++) {
        const int m0 = bm + wm + mt * 16 + g;
        const int r0 = (m0 & 127) * TD + (m0 >> 7);
        const int m1 = m0 + 8;
        const int r1 = (m1 & 127) * TD + (m1 >> 7);
#pragma unroll
        for (int nt = 0; nt < 4; nt++) {
            const int n0 = bn + wn + nt * 8 + 2 * tg;
            if (n0 < VV) {
                const float bv_0 = bias[n0], bv_1 = bias[n0 + 1];
                C[(size_t)r0 * VV + n0]     = acc[mt][nt][0] + bv_0;
                C[(size_t)r0 * VV + n0 + 1] = acc[mt][nt][1] + bv_1;
                C[(size_t)r1 * VV + n0]     = acc[mt][nt][2] + bv_0;
                C[(size_t)r1 * VV + n0 + 1] = acc[mt][nt][3] + bv_1;
            }
        }
    }
}

// NOTE: to_tf32 removed — HW MMA reads tf32 from fp32 bits by truncation inside HMMA;
// ptx mma tf32 ignores low mantissa bits, so explicit cvt is unnecessary.

// ---------------- generic SGEMM-NT ----------------
__global__ __launch_bounds__(256) void gemm_nt(
    const float* __restrict__ A, int lda, const int* __restrict__ arow,
    const float* __restrict__ B, int ldb, const float* __restrict__ bias,
    float* __restrict__ C, int M, int N, int K, int mode)
{
    __shared__ float As[8][132];
    __shared__ float Bs[8][132];
    const int bn = blockIdx.x * 128;
    const int bm = blockIdx.y * 128;
    const int tid = threadIdx.x;
    const int lr = tid >> 1;
    const int lk = (tid & 1) << 2;
    const int tm = (tid >> 4) << 3;
    const int tn = (tid & 15) << 3;

    const int am = bm + lr;
    const int ar = arow ? arow[am] : am;
    const float* Ap = A + (size_t)ar * lda + lk;
    const int bnr = bn + lr;
    const bool bval = (bnr < N);
    const float* Bp = B + (size_t)(bval ? bnr : 0) * ldb + lk;

    float acc[8][8];
#pragma unroll
    for (int i = 0; i < 8; i++)
#pragma unroll
        for (int j = 0; j < 8; j++) acc[i][j] = 0.f;

    for (int k0 = 0; k0 < K; k0 += 8) {
        float4 av = *(const float4*)(Ap + k0);
        float4 bv = bval ? *(const float4*)(Bp + k0) : make_float4(0.f, 0.f, 0.f, 0.f);
        __syncthreads();
        As[lk + 0][lr] = av.x; As[lk + 1][lr] = av.y; As[lk + 2][lr] = av.z; As[lk + 3][lr] = av.w;
        Bs[lk + 0][lr] = bv.x; Bs[lk + 1][lr] = bv.y; Bs[lk + 2][lr] = bv.z; Bs[lk + 3][lr] = bv.w;
        __syncthreads();
#pragma unroll
        for (int kk = 0; kk < 8; kk++) {
            float a[8], b[8];
            *(float4*)(a)     = *(const float4*)&As[kk][tm];
            *(float4*)(a + 4) = *(const float4*)&As[kk][tm + 4];
            *(float4*)(b)     = *(const float4*)&Bs[kk][tn];
            *(float4*)(b + 4) = *(const float4*)&Bs[kk][tn + 4];
#pragma unroll
            for (int i = 0; i < 8; i++)
#pragma unroll
                for (int j = 0; j < 8; j++)
                    acc[i][j] += a[i] * b[j];
        }
    }
#pragma unroll
    for (int i = 0; i < 8; i++) {
        const int m = bm + tm + i;
#pragma unroll
        for (int j = 0; j < 8; j++) {
            const int n = bn + tn + j;
            if (n < N) {
                float v = acc[i][j] + (bias ? bias[n] : 0.f);
                C[(size_t)m * N + n] = v;
            }
        }
    }
}

// ---------------- encoder step: cp.async double-buffered ----------------
// grid (16,4): j0=bx*32, b0=by*32. 256 thr: tj=tid&15 (j, j+16), tb=tid>>4 (b, b+16).
__global__ __launch_bounds__(256) void enc_step(const float* __restrict__ Whh, int t)
{
    __shared__ float ws[2][128 * 36];   // [buf][(g*32+jl)*36 + k]
    __shared__ float hs[2][32 * 36];    // [buf][bb*36 + k]
    const int tid = threadIdx.x;
    const int tj = tid & 15, tb = tid >> 4;
    const int j0 = blockIdx.x * 32, b0 = blockIdx.y * 32;
    const float* hin = (t & 1) ? g_h1 : g_h0;
    float* hout      = (t & 1) ? g_h0 : g_h1;

    uint32_t wsa0 = (uint32_t)__cvta_generic_to_shared(ws[0]);
    uint32_t wsa1 = (uint32_t)__cvta_generic_to_shared(ws[1]);
    uint32_t hsa0 = (uint32_t)__cvta_generic_to_shared(hs[0]);
    uint32_t hsa1 = (uint32_t)__cvta_generic_to_shared(hs[1]);

    float xr[2][2][4];
#pragma unroll
    for (int jh = 0; jh < 2; jh++)
#pragma unroll
        for (int bi = 0; bi < 2; bi++) {
            int b = b0 + tb + bi * 16, j = j0 + tj + jh * 16;
            const float* xp = g_xg + ((size_t)b * SS + t) * 2048 + j;
            xr[jh][bi][0] = __ldg(xp);
            xr[jh][bi][1] = __ldg(xp + 512);
            xr[jh][bi][2] = __ldg(xp + 1024);
            xr[jh][bi][3] = __ldg(xp + 1536);
        }

#define ENC_LOAD(c) do { \
    int _buf = (c) & 1, _k0 = (c) * 32; \
    uint32_t _wb = _buf ? wsa1 : wsa0, _hb = _buf ? hsa1 : hsa0; \
    _Pragma("unroll") \
    for (int _i = 0; _i < 4; _i++) { \
        int _o = _i * 256 + tid; \
        int _row = _o >> 3, _kq = _o & 7; \
        int _g = _row >> 5, _jl = _row & 31; \
        cpa16(_wb + (unsigned)(_row * 144 + _kq * 16), \
              Whh + (size_t)((_g << 9) + j0 + _jl) * 512 + _k0 + _kq * 4); \
    } \
    { int _bb = tid >> 3, _kq = tid & 7; \
      cpa16(_hb + (unsigned)(_bb * 144 + _kq * 16), \
            hin + (size_t)(b0 + _bb) * 512 + _k0 + _kq * 4); } \
    cpcommit(); \
} while (0)

    float acc[2][2][4];
#pragma unroll
    for (int jh = 0; jh < 2; jh++)
#pragma unroll
        for (int bi = 0; bi < 2; bi++)
#pragma unroll
            for (int g = 0; g < 4; g++) acc[jh][bi][g] = 0.f;

    ENC_LOAD(0);
    for (int c = 0; c < 16; c++) {
        if (c < 15) { ENC_LOAD(c + 1); cpwait<1>(); } else cpwait<0>();
        __syncthreads();
        const float4* wv = (const float4*)ws[c & 1];
        const float4* hv = (const float4*)hs[c & 1];
#pragma unroll
        for (int kq = 0; kq < 8; kq++) {
            float4 h0 = hv[tb * 9 + kq];
            float4 h1 = hv[(tb + 16) * 9 + kq];
#pragma unroll
            for (int g = 0; g < 4; g++)
#pragma unroll
                for (int jh = 0; jh < 2; jh++) {
                    float4 w = wv[(g * 32 + tj + jh * 16) * 9 + kq];
                    acc[jh][0][g] = fmaf(w.x, h0.x, fmaf(w.y, h0.y, fmaf(w.z, h0.z, fmaf(w.w, h0.w, acc[jh][0][g]))));
                    acc[jh][1][g] = fmaf(w.x, h1.x, fmaf(w.y, h1.y, fmaf(w.z, h1.z, fmaf(w.w, h1.w, acc[jh][1][g]))));
                }
        }
        __syncthreads();
    }
#undef ENC_LOAD

#pragma unroll
    for (int jh = 0; jh < 2; jh++)
#pragma unroll
        for (int bi = 0; bi < 2; bi++) {
            int b = b0 + tb + bi * 16, j = j0 + tj + jh * 16;
            float ig = acc[jh][bi][0] + xr[jh][bi][0];
            float fg = acc[jh][bi][1] + xr[jh][bi][1];
            float gg = acc[jh][bi][2] + xr[jh][bi][2];
            float og = acc[jh][bi][3] + xr[jh][bi][3];
            float cp = g_c[b * 512 + j];
            float cn = sig_fast(fg) * cp + sig_fast(ig) * tanh_fast(gg);
            float hn = sig_fast(og) * tanh_fast(cn);
            g_c[b * 512 + j] = cn;
            hout[b * 512 + j] = hn;
            g_enc_out[((size_t)b * SS + t) * 512 + j] = hn;
        }
}

// ---------------- decoder step: K=1024 (ctx || h), cp.async double-buffered ----------------
__global__ __launch_bounds__(256) void dec_step(const float* __restrict__ dWih,
                                                const float* __restrict__ dWhh, int t)
{
    __shared__ float ws[2][128 * 36];
    __shared__ float hs[2][32 * 36];
    const int tid = threadIdx.x;
    const int tj = tid & 15, tb = tid >> 4;
    const int j0 = blockIdx.x * 32, b0 = blockIdx.y * 32;
    const float* hin = (t & 1) ? g_h1 : g_h0;
    float* hout      = (t & 1) ? g_h0 : g_h1;

    uint32_t wsa0 = (uint32_t)__cvta_generic_to_shared(ws[0]);
    uint32_t wsa1 = (uint32_t)__cvta_generic_to_shared(ws[1]);
    uint32_t hsa0 = (uint32_t)__cvta_generic_to_shared(hs[0]);
    uint32_t hsa1 = (uint32_t)__cvta_generic_to_shared(hs[1]);

    float ew[2][2][4];
#pragma unroll
    for (int jh = 0; jh < 2; jh++)
#pragma unroll
        for (int bi = 0; bi < 2; bi++) {
            int b = b0 + tb + bi * 16, j = j0 + tj + jh * 16;
            const float* xp = g_embW + ((size_t)t * BB + b) * 2048 + j;
            ew[jh][bi][0] = __ldg(xp);
            ew[jh][bi][1] = __ldg(xp + 512);
            ew[jh][bi][2] = __ldg(xp + 1024);
            ew[jh][bi][3] = __ldg(xp + 1536);
        }

#define DEC_LOAD(c) do { \
    int _buf = (c) & 1, _kc = (c) * 32; \
    uint32_t _wb = _buf ? wsa1 : wsa0, _hb = _buf ? hsa1 : hsa0; \
    const float* _wsrc; int _wstr; const float* _hsrc; \
    if (_kc < 512) { _wsrc = dWih + 256 + _kc; _wstr = 768; _hsrc = g_ctx + _kc; } \
    else           { _wsrc = dWhh + (_kc - 512); _wstr = 512; _hsrc = hin + (_kc - 512); } \
    _Pragma("unroll") \
    for (int _i = 0; _i < 4; _i++) { \
        int _o = _i * 256 + tid; \
        int _row = _o >> 3, _kq = _o & 7; \
        int _g = _row >> 5, _jl = _row & 31; \
        cpa16(_wb + (unsigned)(_row * 144 + _kq * 16), \
              _wsrc + (size_t)((_g << 9) + j0 + _jl) * _wstr + _kq * 4); \
    } \
    { int _bb = tid >> 3, _kq = tid & 7; \
      cpa16(_hb + (unsigned)(_bb * 144 + _kq * 16), \
            _hsrc + (size_t)(b0 + _bb) * 512 + _kq * 4); } \
    cpcommit(); \
} while (0)

    float acc[2][2][4];
#pragma unroll
    for (int jh = 0; jh < 2; jh++)
#pragma unroll
        for (int bi = 0; bi < 2; bi++)
#pragma unroll
            for (int g = 0; g < 4; g++) acc[jh][bi][g] = 0.f;

    DEC_LOAD(0);
    for (int c = 0; c < 32; c++) {
        if (c < 31) { DEC_LOAD(c + 1); cpwait<1>(); } else cpwait<0>();
        __syncthreads();
        const float4* wv = (const float4*)ws[c & 1];
        const float4* hv = (const float4*)hs[c & 1];
#pragma unroll
        for (int kq = 0; kq < 8; kq++) {
            float4 h0 = hv[tb * 9 + kq];
            float4 h1 = hv[(tb + 16) * 9 + kq];
#pragma unroll
            for (int g = 0; g < 4; g++)
#pragma unroll
                for (int jh = 0; jh < 2; jh++) {
                    float4 w = wv[(g * 32 + tj + jh * 16) * 9 + kq];
                    acc[jh][0][g] = fmaf(w.x, h0.x, fmaf(w.y, h0.y, fmaf(w.z, h0.z, fmaf(w.w, h0.w, acc[jh][0][g]))));
                    acc[jh][1][g] = fmaf(w.x, h1.x, fmaf(w.y, h1.y, fmaf(w.z, h1.z, fmaf(w.w, h1.w, acc[jh][1][g]))));
                }
        }
        __syncthreads();
    }
#undef DEC_LOAD

#pragma unroll
    for (int jh = 0; jh < 2; jh++)
#pragma unroll
        for (int bi = 0; bi < 2; bi++) {
            int b = b0 + tb + bi * 16, j = j0 + tj + jh * 16;
            float ig = acc[jh][bi][0] + ew[jh][bi][0];
            float fg = acc[jh][bi][1] + ew[jh][bi][1];
            float gg = acc[jh][bi][2] + ew[jh][bi][2];
            float og = acc[jh][bi][3] + ew[jh][bi][3];
            float cp = g_c[b * 512 + j];
            float cn = sig_fast(fg) * cp + sig_fast(ig) * tanh_fast(gg);
            float hn = sig_fast(og) * tanh_fast(cn);
            g_c[b * 512 + j] = cn;
            hout[b * 512 + j] = hn;
            g_hs[((size_t)t * BB + b) * 512 + j] = hn;
        }
}

// ---------------- q = h@Wq.T + bq, cp.async version ----------------
__global__ __launch_bounds__(256) void q_step(const float* __restrict__ Wq,
                                              const float* __restrict__ bq, int t)
{
    __shared__ float ws[2][32 * 36];
    __shared__ float hs[2][32 * 36];
    const int tid = threadIdx.x;
    const int tj = tid & 15, tb = tid >> 4;
    const int j0 = blockIdx.x * 32, b0 = blockIdx.y * 32;
    const float* hin = (t & 1) ? g_h1 : g_h0;

    uint32_t wsa0 = (uint32_t)__cvta_generic_to_shared(ws[0]);
    uint32_t wsa1 = (uint32_t)__cvta_generic_to_shared(ws[1]);
    uint32_t hsa0 = (uint32_t)__cvta_generic_to_shared(hs[0]);
    uint32_t hsa1 = (uint32_t)__cvta_generic_to_shared(hs[1]);

#define Q_LOAD(c) do { \
    int _buf = (c) & 1, _k0 = (c) * 32; \
    uint32_t _wb = _buf ? wsa1 : wsa0, _hb = _buf ? hsa1 : hsa0; \
    { int _row = tid >> 3, _kq = tid & 7; \
      cpa16(_wb + (unsigned)(_row * 144 + _kq * 16), \
            Wq + (size_t)(j0 + _row) * 512 + _k0 + _kq * 4); \
      cpa16(_hb + (unsigned)(_row * 144 + _kq * 16), \
            hin + (size_t)(b0 + _row) * 512 + _k0 + _kq * 4); } \
    cpcommit(); \
} while (0)

    float acc[2][2] = {{0.f, 0.f}, {0.f, 0.f}};
    Q_LOAD(0);
    for (int c = 0; c < 16; c++) {
        if (c < 15) { Q_LOAD(c + 1); cpwait<1>(); } else cpwait<0>();
        __syncthreads();
        const float4* wv = (const float4*)ws[c & 1];
        const float4* hv = (const float4*)hs[c & 1];
#pragma unroll
        for (int kq = 0; kq < 8; kq++) {
            float4 h0 = hv[tb * 9 + kq];
            float4 h1 = hv[(tb + 16) * 9 + kq];
#pragma unroll
            for (int jh = 0; jh < 2; jh++) {
                float4 w = wv[(tj + jh * 16) * 9 + kq];
                acc[jh][0] = fmaf(w.x, h0.x, fmaf(w.y, h0.y, fmaf(w.z, h0.z, fmaf(w.w, h0.w, acc[jh][0]))));
                acc[jh][1] = fmaf(w.x, h1.x, fmaf(w.y, h1.y, fmaf(w.z, h1.z, fmaf(w.w, h1.w, acc[jh][1]))));
            }
        }
        __syncthreads();
    }
#undef Q_LOAD

#pragma unroll
    for (int jh = 0; jh < 2; jh++)
#pragma unroll
        for (int bi = 0; bi < 2; bi++) {
            int b = b0 + tb + bi * 16, j = j0 + tj + jh * 16;
            g_q[b * 512 + j] = acc[jh][bi] + bq[j];
        }
}

// ---------------- attention (block per batch element), FMA-only tanh ----------------
__global__ __launch_bounds__(256) void att_step(const float* __restrict__ v_w,
                                                const float* __restrict__ v_b,
                                                const int* __restrict__ src,
                                                float* __restrict__ attn_out,
                                                int t, int writeAttn)
{
    const int b = blockIdx.x;
    const int tid = threadIdx.x;
    __shared__ float qs[512], vs[512], sc[64];
    qs[tid] = g_q[b * 512 + tid];
    qs[tid + 256] = g_q[b * 512 + tid + 256];
    vs[tid] = v_w[tid];
    vs[tid + 256] = v_w[tid + 256];
    __syncthreads();
    const int warp = tid >> 5, lane = tid & 31;
    for (int s = warp; s < 64; s += 8) {
        const float* kp = g_keys + ((size_t)b * SS + s) * 512;
        float sum = 0.f;
#pragma unroll 4
        for (int j = lane; j < 512; j += 32)
            sum += tanh_fast(qs[j] + kp[j]) * vs[j];
#pragma unroll
        for (int o = 16; o; o >>= 1) sum += __shfl_xor_sync(0xffffffffu, sum, o);
        if (lane == 0) {
            sum += v_b[0];
            if (src[b * SS + s] == 0) sum = -1e9f;
            sc[s] = sum;
        }
    }
    __syncthreads();
    if (warp == 0) {
        float a0 = sc[lane], a1 = sc[lane + 32];
        float m = fmaxf(a0, a1);
#pragma unroll
        for (int o = 16; o; o >>= 1) m = fmaxf(m, __shfl_xor_sync(0xffffffffu, m, o));
        float e0 = exp_fast(a0 - m), e1 = exp_fast(a1 - m);
        float ss = e0 + e1;
#pragma unroll
        for (int o = 16; o; o >>= 1) ss += __shfl_xor_sync(0xffffffffu, ss, o);
        float inv = rcp_fast(ss);
        sc[lane] = e0 * inv;
        sc[lane + 32] = e1 * inv;
        if (writeAttn) {
            attn_out[((size_t)b * TD + t) * SS + lane] = e0 * inv;
            attn_out[((size_t)b * TD + t) * SS + lane + 32] = e1 * inv;
        }
    }
    __syncthreads();
    for (int j = tid; j < 512; j += 256) {
        float a = 0.f;
        const float* ep = g_enc_out + (size_t)b * SS * 512 + j;
#pragma unroll 8
        for (int s = 0; s < 64; s++) a += sc[s] * ep[(size_t)s * 512];
        g_ctx[b * 512 + j] = a;
    }
}

// ---------------- small helpers ----------------
__global__ void zero_hc()
{
    int i = blockIdx.x * 256 + threadIdx.x;
    g_h0[i] = 0.f;
    g_c[i] = 0.f;
}

__global__ void build_rows(const int* __restrict__ tgt)
{
    int i = blockIdx.x * 256 + threadIdx.x;
    if (i < TD * BB) {
        int tt = i >> 7, b = i & 127;
        g_rows[i] = (tt == 0) ? 1 : tgt[b * 33 + tt];
    }
}

// ---------------- launch ----------------
extern "C" void kernel_launch(void* const* d_in, const int* in_sizes, int n_in,
                              void* d_out, int out_size)
{
    (void)in_sizes; (void)n_in;
    const int*   src     = (const int*)d_in[0];
    const int*   tgt     = (const int*)d_in[1];
    const float* enc_emb = (const float*)d_in[2];
    const float* enc_Wih = (const float*)d_in[3];
    const float* enc_Whh = (const float*)d_in[4];
    const float* enc_b   = (const float*)d_in[5];
    const float* dec_emb = (const float*)d_in[6];
    const float* Wq      = (const float*)d_in[7];
    const float* bq      = (const float*)d_in[8];
    const float* Wk      = (const float*)d_in[9];
    const float* bk      = (const float*)d_in[10];
    const float* v_w     = (const float*)d_in[11];
    const float* v_b     = (const float*)d_in[12];
    const float* dWih    = (const float*)d_in[13];
    const float* dWhh    = (const float*)d_in[14];
    const float* db      = (const float*)d_in[15];
    const float* Wo      = (const float*)d_in[16];
    const float* bo      = (const float*)d_in[17];
    float* out = (float*)d_out;

    void *p_xg, *p_enc, *p_keys, *p_embW, *p_hs, *p_rows;
    cudaGetSymbolAddress(&p_xg,   g_xg);
    cudaGetSymbolAddress(&p_enc,  g_enc_out);
    cudaGetSymbolAddress(&p_keys, g_keys);
    cudaGetSymbolAddress(&p_embW, g_embW);
    cudaGetSymbolAddress(&p_hs,   g_hs);
    cudaGetSymbolAddress(&p_rows, g_rows);

    zero_hc<<<256, 256>>>();

    gemm_nt<<<dim3(16, 64), 256>>>(enc_emb, 256, src, enc_Wih, 256, enc_b,
                                   (float*)p_xg, 8192, 2048, 256, 0);
    build_rows<<<16, 256>>>(tgt);
    gemm_nt<<<dim3(16, 32), 256>>>(dec_emb, 256, (const int*)p_rows, dWih, 768, db,
                                   (float*)p_embW, 4096, 2048, 256, 0);

    for (int t = 0; t < SS; t++)
        enc_step<<<dim3(16, 4), 256>>>(enc_Whh, t);

    gemm_nt<<<dim3(4, 64), 256>>>((const float*)p_enc, 512, nullptr, Wk, 512, bk,
                                  (float*)p_keys, 8192, 512, 512, 0);

    const long long LOGITS = (long long)BB * TD * VV;
    const long long TOTAL  = LOGITS + (long long)BB * TD * SS;
    int writeAttn = ((long long)out_size >= TOTAL);
    float* attn = out + LOGITS;

    for (int t = 0; t < TD; t++) {
        q_step<<<dim3(16, 4), 256>>>(Wq, bq, t);
        att_step<<<128, 256>>>(v_w, v_b, src, attn, t, writeAttn);
        dec_step<<<dim3(16, 4), 256>>>(dWih, dWhh, t);
    }

    gemm_tf32_logits<<<dim3(157, 32), 256>>>((const float*)p_hs, Wo, bo, out);
}

// round 6
// speedup vs baseline: 1.5147x; 1.5147x over previous
#include <cuda_runtime.h>
#include <math.h>
#include <stdint.h>

#define VV 20000
#define HH 512
#define BB 128
#define SS 64
#define TD 32

// ---------------- scratch (device globals) ----------------
__device__ float g_xg[BB * SS * 2048];
__device__ float g_enc_out[BB * SS * HH];
__device__ float g_keys[BB * SS * HH];
__device__ float g_embW[TD * BB * 2048];
__device__ float g_hs[TD * BB * HH];
__device__ float g_h0[BB * HH];
__device__ float g_h1[BB * HH];
__device__ float g_c[BB * HH];
__device__ float g_q[BB * HH];
__device__ float g_ctx[BB * HH];
__device__ int   g_rows[TD * BB];
__device__ float g_part[2 * 64 * 4096];   // split-K partials [kz][tile][tid*16+idx]
__device__ unsigned g_ctr[64];            // per-tile arrival counters (always 0 at kernel boundaries)

// ---------------- MUFU-free transcendentals ----------------
__device__ __forceinline__ float exp_fast(float x) {
    x = fminf(fmaxf(x, -87.f), 87.f);
    float y = x * 1.4426950408889634f;
    float fl = floorf(y);
    float f = y - fl;
    float p =              1.3215486790e-6f;
    p = fmaf(p, f, 1.5252733804e-5f);
    p = fmaf(p, f, 1.5403530394e-4f);
    p = fmaf(p, f, 1.3333558146e-3f);
    p = fmaf(p, f, 9.6181291076e-3f);
    p = fmaf(p, f, 5.5504108664e-2f);
    p = fmaf(p, f, 2.4022650696e-1f);
    p = fmaf(p, f, 6.9314718056e-1f);
    p = fmaf(p, f, 1.0f);
    int i = (int)fl;
    return __int_as_float((i + 127) << 23) * p;
}
__device__ __forceinline__ float rcp_fast(float d) {
    float r = __uint_as_float(0x7EF311C3u - __float_as_uint(d));
    r = r * fmaf(-d, r, 2.0f);
    r = r * fmaf(-d, r, 2.0f);
    r = r * fmaf(-d, r, 2.0f);
    return r;
}
__device__ __forceinline__ float sig_fast(float x) {
    return rcp_fast(1.0f + exp_fast(-x));
}
__device__ __forceinline__ float tanh_fast(float x) {
    float a = fabsf(x);
    float t = exp_fast(-2.0f * a);
    float r = (1.0f - t) * rcp_fast(1.0f + t);
    return copysignf(r, x);
}
__device__ __forceinline__ float to_tf32(float x) {
    float y; asm("cvt.rna.tf32.f32 %0, %1;" : "=f"(y) : "f"(x)); return y;
}

// ================= TF32 MMA logits GEMM (R4-validated, rna rounding) =================
#define LST 136
__global__ __launch_bounds__(256) void gemm_tf32_logits(
    const float* __restrict__ A, const float* __restrict__ B,
    const float* __restrict__ bias, float* __restrict__ C)
{
    __shared__ float As[2][16][LST];
    __shared__ float Bs[2][16][LST];
    const int bm = blockIdx.y * 128;
    const int bn = blockIdx.x * 128;
    const int tid = threadIdx.x;
    const int warp = tid >> 5, lane = tid & 31;
    const int wm = (warp >> 2) * 64, wn = (warp & 3) * 32;
    const int g = lane >> 2, tg = lane & 3;

    const int lr = tid & 127;
    const int lc = tid >> 7;
    const float* Ap = A + (size_t)(bm + lr) * 512 + lc * 4;
    const int bnr = bn + lr;
    const bool bok = (bnr < VV);
    const float* Bp = B + (size_t)(bok ? bnr : 0) * 512 + lc * 4;

    float acc[4][4][4];
#pragma unroll
    for (int mt = 0; mt < 4; mt++)
#pragma unroll
        for (int nt = 0; nt < 4; nt++)
#pragma unroll
            for (int i = 0; i < 4; i++) acc[mt][nt][i] = 0.f;

    float4 av0 = *(const float4*)(Ap);
    float4 av1 = *(const float4*)(Ap + 8);
    float4 bv0 = bok ? *(const float4*)(Bp)     : make_float4(0.f,0.f,0.f,0.f);
    float4 bv1 = bok ? *(const float4*)(Bp + 8) : make_float4(0.f,0.f,0.f,0.f);

#define STORE_T(buf) do { \
    As[buf][lc*4+0][lr]=to_tf32(av0.x); As[buf][lc*4+1][lr]=to_tf32(av0.y); \
    As[buf][lc*4+2][lr]=to_tf32(av0.z); As[buf][lc*4+3][lr]=to_tf32(av0.w); \
    As[buf][lc*4+8][lr]=to_tf32(av1.x); As[buf][lc*4+9][lr]=to_tf32(av1.y); \
    As[buf][lc*4+10][lr]=to_tf32(av1.z); As[buf][lc*4+11][lr]=to_tf32(av1.w); \
    Bs[buf][lc*4+0][lr]=to_tf32(bv0.x); Bs[buf][lc*4+1][lr]=to_tf32(bv0.y); \
    Bs[buf][lc*4+2][lr]=to_tf32(bv0.z); Bs[buf][lc*4+3][lr]=to_tf32(bv0.w); \
    Bs[buf][lc*4+8][lr]=to_tf32(bv1.x); Bs[buf][lc*4+9][lr]=to_tf32(bv1.y); \
    Bs[buf][lc*4+10][lr]=to_tf32(bv1.z); Bs[buf][lc*4+11][lr]=to_tf32(bv1.w); \
} while(0)

    STORE_T(0);
    __syncthreads();

    for (int kb = 0; kb < 32; kb++) {
        const int cur = kb & 1;
        if (kb < 31) {
            const float* Ap2 = Ap + (kb + 1) * 16;
            const float* Bp2 = Bp + (kb + 1) * 16;
            av0 = *(const float4*)(Ap2);
            av1 = *(const float4*)(Ap2 + 8);
            bv0 = bok ? *(const float4*)(Bp2)     : make_float4(0.f,0.f,0.f,0.f);
            bv1 = bok ? *(const float4*)(Bp2 + 8) : make_float4(0.f,0.f,0.f,0.f);
        }
#pragma unroll
        for (int ks = 0; ks < 2; ks++) {
            const int k = ks * 8;
            unsigned afr[4][4], bfr[4][2];
#pragma unroll
            for (int mt = 0; mt < 4; mt++) {
                const int m = wm + mt * 16 + g;
                afr[mt][0] = __float_as_uint(As[cur][k + tg][m]);
                afr[mt][1] = __float_as_uint(As[cur][k + tg][m + 8]);
                afr[mt][2] = __float_as_uint(As[cur][k + tg + 4][m]);
                afr[mt][3] = __float_as_uint(As[cur][k + tg + 4][m + 8]);
            }
#pragma unroll
            for (int nt = 0; nt < 4; nt++) {
                const int n = wn + nt * 8 + g;
                bfr[nt][0] = __float_as_uint(Bs[cur][k + tg][n]);
                bfr[nt][1] = __float_as_uint(Bs[cur][k + tg + 4][n]);
            }
#pragma unroll
            for (int mt = 0; mt < 4; mt++)
#pragma unroll
                for (int nt = 0; nt < 4; nt++) {
                    asm volatile(
                        "mma.sync.aligned.m16n8k8.row.col.f32.tf32.tf32.f32 "
                        "{%0,%1,%2,%3}, {%4,%5,%6,%7}, {%8,%9}, {%0,%1,%2,%3};"
                        : "+f"(acc[mt][nt][0]), "+f"(acc[mt][nt][1]),
                          "+f"(acc[mt][nt][2]), "+f"(acc[mt][nt][3])
                        : "r"(afr[mt][0]), "r"(afr[mt][1]), "r"(afr[mt][2]), "r"(afr[mt][3]),
                          "r"(bfr[nt][0]), "r"(bfr[nt][1]));
                }
        }
        __syncthreads();
        if (kb < 31) {
            STORE_T(cur ^ 1);
            __syncthreads();
        }
    }

#pragma unroll
    for (int mt = 0; mt < 4; mt++) {
        const int m0 = bm + wm + mt * 16 + g;
        const int r0 = (m0 & 127) * TD + (m0 >> 7);
        const int m1 = m0 + 8;
        const int r1 = (m1 & 127) * TD + (m1 >> 7);
#pragma unroll
        for (int nt = 0; nt < 4; nt++) {
            const int n0 = bn + wn + nt * 8 + 2 * tg;
            if (n0 < VV) {
                const float bv_0 = bias[n0], bv_1 = bias[n0 + 1];
                C[(size_t)r0 * VV + n0]     = acc[mt][nt][0] + bv_0;
                C[(size_t)r0 * VV + n0 + 1] = acc[mt][nt][1] + bv_1;
                C[(size_t)r1 * VV + n0]     = acc[mt][nt][2] + bv_0;
                C[(size_t)r1 * VV + n0 + 1] = acc[mt][nt][3] + bv_1;
            }
        }
    }
}

// ---------------- generic SGEMM-NT ----------------
__global__ __launch_bounds__(256) void gemm_nt(
    const float* __restrict__ A, int lda, const int* __restrict__ arow,
    const float* __restrict__ B, int ldb, const float* __restrict__ bias,
    float* __restrict__ C, int M, int N, int K, int mode)
{
    __shared__ float As[8][132];
    __shared__ float Bs[8][132];
    const int bn = blockIdx.x * 128;
    const int bm = blockIdx.y * 128;
    const int tid = threadIdx.x;
    const int lr = tid >> 1;
    const int lk = (tid & 1) << 2;
    const int tm = (tid >> 4) << 3;
    const int tn = (tid & 15) << 3;

    const int am = bm + lr;
    const int ar = arow ? arow[am] : am;
    const float* Ap = A + (size_t)ar * lda + lk;
    const int bnr = bn + lr;
    const bool bval = (bnr < N);
    const float* Bp = B + (size_t)(bval ? bnr : 0) * ldb + lk;

    float acc[8][8];
#pragma unroll
    for (int i = 0; i < 8; i++)
#pragma unroll
        for (int j = 0; j < 8; j++) acc[i][j] = 0.f;

    for (int k0 = 0; k0 < K; k0 += 8) {
        float4 av = *(const float4*)(Ap + k0);
        float4 bv = bval ? *(const float4*)(Bp + k0) : make_float4(0.f, 0.f, 0.f, 0.f);
        __syncthreads();
        As[lk + 0][lr] = av.x; As[lk + 1][lr] = av.y; As[lk + 2][lr] = av.z; As[lk + 3][lr] = av.w;
        Bs[lk + 0][lr] = bv.x; Bs[lk + 1][lr] = bv.y; Bs[lk + 2][lr] = bv.z; Bs[lk + 3][lr] = bv.w;
        __syncthreads();
#pragma unroll
        for (int kk = 0; kk < 8; kk++) {
            float a[8], b[8];
            *(float4*)(a)     = *(const float4*)&As[kk][tm];
            *(float4*)(a + 4) = *(const float4*)&As[kk][tm + 4];
            *(float4*)(b)     = *(const float4*)&Bs[kk][tn];
            *(float4*)(b + 4) = *(const float4*)&Bs[kk][tn + 4];
#pragma unroll
            for (int i = 0; i < 8; i++)
#pragma unroll
                for (int j = 0; j < 8; j++)
                    acc[i][j] += a[i] * b[j];
        }
    }
#pragma unroll
    for (int i = 0; i < 8; i++) {
        const int m = bm + tm + i;
#pragma unroll
        for (int j = 0; j < 8; j++) {
            const int n = bn + tn + j;
            if (n < N) {
                float v = acc[i][j] + (bias ? bias[n] : 0.f);
                C[(size_t)m * N + n] = v;
            }
        }
    }
}

// ---------------- encoder step: R1 body + split-K over 2 blocks ----------------
// grid (16,4,2): 32j x 32b tile, kz halves K. Last-arriving block does the cell.
__global__ __launch_bounds__(256) void enc_step(const float* __restrict__ Whh, int t)
{
    __shared__ float hs[32][34];
    __shared__ float ws[4][32][34];
    __shared__ unsigned s_old;
    const int tid = threadIdx.x;
    const int tj = tid & 15;
    const int tb = tid >> 4;
    const int j0 = blockIdx.x * 32;
    const int b0 = blockIdx.y * 32;
    const int kz = blockIdx.z;
    const int tile = blockIdx.y * 16 + blockIdx.x;
    const float* hin = (t & 1) ? g_h1 : g_h0;
    float* hout      = (t & 1) ? g_h0 : g_h1;

    float acc[4][2][2];
#pragma unroll
    for (int g = 0; g < 4; g++) { acc[g][0][0] = acc[g][0][1] = acc[g][1][0] = acc[g][1][1] = 0.f; }

    for (int c = 0; c < 8; c++) {
        const int k0 = kz * 256 + c * 32;
        __syncthreads();
#pragma unroll
        for (int i = 0; i < 4; i++) {
            int idx = i * 256 + tid;
            int bb = idx >> 5, kk = idx & 31;
            hs[kk][bb] = hin[(size_t)(b0 + bb) * 512 + k0 + kk];
        }
#pragma unroll
        for (int i = 0; i < 16; i++) {
            int idx = i * 256 + tid;
            int g = idx >> 10, jj = (idx >> 5) & 31, kk = idx & 31;
            ws[g][kk][jj] = Whh[(size_t)((g << 9) + j0 + jj) * 512 + k0 + kk];
        }
        __syncthreads();
#pragma unroll
        for (int kk = 0; kk < 32; kk++) {
            float2 hp = *(const float2*)&hs[kk][tb * 2];
#pragma unroll
            for (int g = 0; g < 4; g++) {
                float2 wp = *(const float2*)&ws[g][kk][tj * 2];
                acc[g][0][0] += hp.x * wp.x;
                acc[g][0][1] += hp.x * wp.y;
                acc[g][1][0] += hp.y * wp.x;
                acc[g][1][1] += hp.y * wp.y;
            }
        }
    }

    // publish partials, then arbitrate (threadFenceReduction pattern)
    float* myp = g_part + ((size_t)kz * 64 + tile) * 4096 + tid * 16;
#pragma unroll
    for (int g = 0; g < 4; g++)
#pragma unroll
        for (int bi = 0; bi < 2; bi++)
#pragma unroll
            for (int ji = 0; ji < 2; ji++)
                myp[g * 4 + bi * 2 + ji] = acc[g][bi][ji];
    __threadfence();
    __syncthreads();
    if (tid == 0) s_old = atomicAdd(&g_ctr[tile], 1u);
    __syncthreads();
    if (s_old == 0) return;     // first arriver exits; no spinning

    // winner: combine own regs + other half's partials, run cell
    const float* op = g_part + ((size_t)(1 - kz) * 64 + tile) * 4096 + tid * 16;
#pragma unroll
    for (int bi = 0; bi < 2; bi++)
#pragma unroll
        for (int ji = 0; ji < 2; ji++) {
            const int b = b0 + tb * 2 + bi;
            const int j = j0 + tj * 2 + ji;
            const size_t xb = ((size_t)b * SS + t) * 2048 + j;
            float ig = acc[0][bi][ji] + __ldcg(&op[0  + bi * 2 + ji]) + g_xg[xb];
            float fg = acc[1][bi][ji] + __ldcg(&op[4  + bi * 2 + ji]) + g_xg[xb + 512];
            float gg = acc[2][bi][ji] + __ldcg(&op[8  + bi * 2 + ji]) + g_xg[xb + 1024];
            float og = acc[3][bi][ji] + __ldcg(&op[12 + bi * 2 + ji]) + g_xg[xb + 1536];
            float cp = g_c[b * 512 + j];
            float cn = sig_fast(fg) * cp + sig_fast(ig) * tanh_fast(gg);
            float hn = sig_fast(og) * tanh_fast(cn);
            g_c[b * 512 + j] = cn;
            hout[b * 512 + j] = hn;
            g_enc_out[((size_t)b * SS + t) * 512 + j] = hn;
        }
    if (tid == 0) atomicExch(&g_ctr[tile], 0u);   // restore for next launch
}

// ---------------- decoder step: split kz=0 -> ctx@dWih, kz=1 -> h@dWhh ----------------
__global__ __launch_bounds__(256) void dec_step(const float* __restrict__ dWih,
                                                const float* __restrict__ dWhh, int t)
{
    __shared__ float hs[32][34];
    __shared__ float ws[4][32][34];
    __shared__ unsigned s_old;
    const int tid = threadIdx.x;
    const int tj = tid & 15;
    const int tb = tid >> 4;
    const int j0 = blockIdx.x * 32;
    const int b0 = blockIdx.y * 32;
    const int kz = blockIdx.z;
    const int tile = blockIdx.y * 16 + blockIdx.x;
    const float* hin = (t & 1) ? g_h1 : g_h0;
    float* hout      = (t & 1) ? g_h0 : g_h1;
    const float* src = kz ? hin : g_ctx;

    float acc[4][2][2];
#pragma unroll
    for (int g = 0; g < 4; g++) { acc[g][0][0] = acc[g][0][1] = acc[g][1][0] = acc[g][1][1] = 0.f; }

    for (int c = 0; c < 16; c++) {
        const int k0 = c * 32;
        __syncthreads();
#pragma unroll
        for (int i = 0; i < 4; i++) {
            int idx = i * 256 + tid;
            int bb = idx >> 5, kk = idx & 31;
            hs[kk][bb] = src[(size_t)(b0 + bb) * 512 + k0 + kk];
        }
#pragma unroll
        for (int i = 0; i < 16; i++) {
            int idx = i * 256 + tid;
            int g = idx >> 10, jj = (idx >> 5) & 31, kk = idx & 31;
            int n = (g << 9) + j0 + jj;
            ws[g][kk][jj] = kz ? dWhh[(size_t)n * 512 + k0 + kk]
                               : dWih[(size_t)n * 768 + 256 + k0 + kk];
        }
        __syncthreads();
#pragma unroll
        for (int kk = 0; kk < 32; kk++) {
            float2 hp = *(const float2*)&hs[kk][tb * 2];
#pragma unroll
            for (int g = 0; g < 4; g++) {
                float2 wp = *(const float2*)&ws[g][kk][tj * 2];
                acc[g][0][0] += hp.x * wp.x;
                acc[g][0][1] += hp.x * wp.y;
                acc[g][1][0] += hp.y * wp.x;
                acc[g][1][1] += hp.y * wp.y;
            }
        }
    }

    float* myp = g_part + ((size_t)kz * 64 + tile) * 4096 + tid * 16;
#pragma unroll
    for (int g = 0; g < 4; g++)
#pragma unroll
        for (int bi = 0; bi < 2; bi++)
#pragma unroll
            for (int ji = 0; ji < 2; ji++)
                myp[g * 4 + bi * 2 + ji] = acc[g][bi][ji];
    __threadfence();
    __syncthreads();
    if (tid == 0) s_old = atomicAdd(&g_ctr[tile], 1u);
    __syncthreads();
    if (s_old == 0) return;

    const float* op = g_part + ((size_t)(1 - kz) * 64 + tile) * 4096 + tid * 16;
#pragma unroll
    for (int bi = 0; bi < 2; bi++)
#pragma unroll
        for (int ji = 0; ji < 2; ji++) {
            const int b = b0 + tb * 2 + bi;
            const int j = j0 + tj * 2 + ji;
            const size_t mb = ((size_t)t * BB + b) * 2048 + j;
            float ig = acc[0][bi][ji] + __ldcg(&op[0  + bi * 2 + ji]) + g_embW[mb];
            float fg = acc[1][bi][ji] + __ldcg(&op[4  + bi * 2 + ji]) + g_embW[mb + 512];
            float gg = acc[2][bi][ji] + __ldcg(&op[8  + bi * 2 + ji]) + g_embW[mb + 1024];
            float og = acc[3][bi][ji] + __ldcg(&op[12 + bi * 2 + ji]) + g_embW[mb + 1536];
            float cp = g_c[b * 512 + j];
            float cn = sig_fast(fg) * cp + sig_fast(ig) * tanh_fast(gg);
            float hn = sig_fast(og) * tanh_fast(cn);
            g_c[b * 512 + j] = cn;
            hout[b * 512 + j] = hn;
            g_hs[((size_t)t * BB + b) * 512 + j] = hn;
        }
    if (tid == 0) atomicExch(&g_ctr[tile], 0u);
}

// ---------------- q = h@Wq.T + bq (R1 version) ----------------
__global__ __launch_bounds__(256) void q_step(const float* __restrict__ Wq,
                                              const float* __restrict__ bq, int t)
{
    __shared__ float hs[32][34];
    __shared__ float ws[32][34];
    const int tid = threadIdx.x;
    const int tj = tid & 15;
    const int tb = tid >> 4;
    const int j0 = blockIdx.x * 32;
    const int b0 = blockIdx.y * 32;
    const float* hin = (t & 1) ? g_h1 : g_h0;

    float acc[2][2] = {{0.f, 0.f}, {0.f, 0.f}};
    for (int k0 = 0; k0 < 512; k0 += 32) {
        __syncthreads();
#pragma unroll
        for (int i = 0; i < 4; i++) {
            int idx = i * 256 + tid;
            int bb = idx >> 5, kk = idx & 31;
            hs[kk][bb] = hin[(size_t)(b0 + bb) * 512 + k0 + kk];
        }
#pragma unroll
        for (int i = 0; i < 4; i++) {
            int idx = i * 256 + tid;
            int jj = idx >> 5, kk = idx & 31;
            ws[kk][jj] = Wq[(size_t)(j0 + jj) * 512 + k0 + kk];
        }
        __syncthreads();
#pragma unroll
        for (int kk = 0; kk < 32; kk++) {
            float2 hp = *(const float2*)&hs[kk][tb * 2];
            float2 wp = *(const float2*)&ws[kk][tj * 2];
            acc[0][0] += hp.x * wp.x;
            acc[0][1] += hp.x * wp.y;
            acc[1][0] += hp.y * wp.x;
            acc[1][1] += hp.y * wp.y;
        }
    }
#pragma unroll
    for (int bi = 0; bi < 2; bi++)
#pragma unroll
        for (int ji = 0; ji < 2; ji++) {
            const int b = b0 + tb * 2 + bi;
            const int j = j0 + tj * 2 + ji;
            g_q[b * 512 + j] = acc[bi][ji] + bq[j];
        }
}

// ---------------- attention (FMA-only transcendentals) ----------------
__global__ __launch_bounds__(256) void att_step(const float* __restrict__ v_w,
                                                const float* __restrict__ v_b,
                                                const int* __restrict__ src,
                                                float* __restrict__ attn_out,
                                                int t, int writeAttn)
{
    const int b = blockIdx.x;
    const int tid = threadIdx.x;
    __shared__ float qs[512], vs[512], sc[64];
    qs[tid] = g_q[b * 512 + tid];
    qs[tid + 256] = g_q[b * 512 + tid + 256];
    vs[tid] = v_w[tid];
    vs[tid + 256] = v_w[tid + 256];
    __syncthreads();
    const int warp = tid >> 5, lane = tid & 31;
    for (int s = warp; s < 64; s += 8) {
        const float* kp = g_keys + ((size_t)b * SS + s) * 512;
        float sum = 0.f;
#pragma unroll 4
        for (int j = lane; j < 512; j += 32)
            sum += tanh_fast(qs[j] + kp[j]) * vs[j];
#pragma unroll
        for (int o = 16; o; o >>= 1) sum += __shfl_xor_sync(0xffffffffu, sum, o);
        if (lane == 0) {
            sum += v_b[0];
            if (src[b * SS + s] == 0) sum = -1e9f;
            sc[s] = sum;
        }
    }
    __syncthreads();
    if (warp == 0) {
        float a0 = sc[lane], a1 = sc[lane + 32];
        float m = fmaxf(a0, a1);
#pragma unroll
        for (int o = 16; o; o >>= 1) m = fmaxf(m, __shfl_xor_sync(0xffffffffu, m, o));
        float e0 = exp_fast(a0 - m), e1 = exp_fast(a1 - m);
        float ss = e0 + e1;
#pragma unroll
        for (int o = 16; o; o >>= 1) ss += __shfl_xor_sync(0xffffffffu, ss, o);
        float inv = rcp_fast(ss);
        sc[lane] = e0 * inv;
        sc[lane + 32] = e1 * inv;
        if (writeAttn) {
            attn_out[((size_t)b * TD + t) * SS + lane] = e0 * inv;
            attn_out[((size_t)b * TD + t) * SS + lane + 32] = e1 * inv;
        }
    }
    __syncthreads();
    for (int j = tid; j < 512; j += 256) {
        float a = 0.f;
        const float* ep = g_enc_out + (size_t)b * SS * 512 + j;
#pragma unroll 8
        for (int s = 0; s < 64; s++) a += sc[s] * ep[(size_t)s * 512];
        g_ctx[b * 512 + j] = a;
    }
}

// ---------------- small helpers ----------------
__global__ void zero_hc()
{
    int i = blockIdx.x * 256 + threadIdx.x;   // grid 256 -> 65536
    g_h0[i] = 0.f;
    g_c[i] = 0.f;
    if (i < 64) g_ctr[i] = 0u;
}

__global__ void build_rows(const int* __restrict__ tgt)
{
    int i = blockIdx.x * 256 + threadIdx.x;
    if (i < TD * BB) {
        int tt = i >> 7, b = i & 127;
        g_rows[i] = (tt == 0) ? 1 : tgt[b * 33 + tt];
    }
}

// ---------------- launch ----------------
extern "C" void kernel_launch(void* const* d_in, const int* in_sizes, int n_in,
                              void* d_out, int out_size)
{
    (void)in_sizes; (void)n_in;
    const int*   src     = (const int*)d_in[0];
    const int*   tgt     = (const int*)d_in[1];
    const float* enc_emb = (const float*)d_in[2];
    const float* enc_Wih = (const float*)d_in[3];
    const float* enc_Whh = (const float*)d_in[4];
    const float* enc_b   = (const float*)d_in[5];
    const float* dec_emb = (const float*)d_in[6];
    const float* Wq      = (const float*)d_in[7];
    const float* bq      = (const float*)d_in[8];
    const float* Wk      = (const float*)d_in[9];
    const float* bk      = (const float*)d_in[10];
    const float* v_w     = (const float*)d_in[11];
    const float* v_b     = (const float*)d_in[12];
    const float* dWih    = (const float*)d_in[13];
    const float* dWhh    = (const float*)d_in[14];
    const float* db      = (const float*)d_in[15];
    const float* Wo      = (const float*)d_in[16];
    const float* bo      = (const float*)d_in[17];
    float* out = (float*)d_out;

    void *p_xg, *p_enc, *p_keys, *p_embW, *p_hs, *p_rows;
    cudaGetSymbolAddress(&p_xg,   g_xg);
    cudaGetSymbolAddress(&p_enc,  g_enc_out);
    cudaGetSymbolAddress(&p_keys, g_keys);
    cudaGetSymbolAddress(&p_embW, g_embW);
    cudaGetSymbolAddress(&p_hs,   g_hs);
    cudaGetSymbolAddress(&p_rows, g_rows);

    zero_hc<<<256, 256>>>();

    gemm_nt<<<dim3(16, 64), 256>>>(enc_emb, 256, src, enc_Wih, 256, enc_b,
                                   (float*)p_xg, 8192, 2048, 256, 0);
    build_rows<<<16, 256>>>(tgt);
    gemm_nt<<<dim3(16, 32), 256>>>(dec_emb, 256, (const int*)p_rows, dWih, 768, db,
                                   (float*)p_embW, 4096, 2048, 256, 0);

    for (int t = 0; t < SS; t++)
        enc_step<<<dim3(16, 4, 2), 256>>>(enc_Whh, t);

    gemm_nt<<<dim3(4, 64), 256>>>((const float*)p_enc, 512, nullptr, Wk, 512, bk,
                                  (float*)p_keys, 8192, 512, 512, 0);

    const long long LOGITS = (long long)BB * TD * VV;
    const long long TOTAL  = LOGITS + (long long)BB * TD * SS;
    int writeAttn = ((long long)out_size >= TOTAL);
    float* attn = out + LOGITS;

    for (int t = 0; t < TD; t++) {
        q_step<<<dim3(16, 4), 256>>>(Wq, bq, t);
        att_step<<<128, 256>>>(v_w, v_b, src, attn, t, writeAttn);
        dec_step<<<dim3(16, 4, 2), 256>>>(dWih, dWhh, t);
    }

    gemm_tf32_logits<<<dim3(157, 32), 256>>>((const float*)p_hs, Wo, bo, out);
}

// round 12
// speedup vs baseline: 1.5213x; 1.0044x over previous
#include <cuda_runtime.h>
#include <math.h>
#include <stdint.h>

#define VV 20000
#define HH 512
#define BB 128
#define SS 64
#define TD 32

// ---------------- scratch (device globals) ----------------
__device__ float g_xg[BB * SS * 2048];
__device__ float g_enc_out[BB * SS * HH];
__device__ float g_keys[BB * SS * HH];
__device__ float g_embW[TD * BB * 2048];
__device__ float g_hs[TD * BB * HH];
__device__ float g_h0[BB * HH];
__device__ float g_h1[BB * HH];
__device__ float g_c[BB * HH];
__device__ float g_q[BB * HH];
__device__ float g_ctx[BB * HH];
__device__ int   g_rows[TD * BB];
__device__ float g_part[2 * 64 * 4096];
__device__ unsigned g_ctr[64];
__device__ float g_wor[VV * HH];          // tf32-pre-rounded Wo
__device__ float g_hsr[TD * BB * HH];     // tf32-pre-rounded hs

// ---------------- MUFU-free transcendentals ----------------
__device__ __forceinline__ float exp_fast(float x) {
    x = fminf(fmaxf(x, -87.f), 87.f);
    float y = x * 1.4426950408889634f;
    float fl = floorf(y);
    float f = y - fl;
    float p =              1.3215486790e-6f;
    p = fmaf(p, f, 1.5252733804e-5f);
    p = fmaf(p, f, 1.5403530394e-4f);
    p = fmaf(p, f, 1.3333558146e-3f);
    p = fmaf(p, f, 9.6181291076e-3f);
    p = fmaf(p, f, 5.5504108664e-2f);
    p = fmaf(p, f, 2.4022650696e-1f);
    p = fmaf(p, f, 6.9314718056e-1f);
    p = fmaf(p, f, 1.0f);
    int i = (int)fl;
    return __int_as_float((i + 127) << 23) * p;
}
__device__ __forceinline__ float rcp_fast(float d) {
    float r = __uint_as_float(0x7EF311C3u - __float_as_uint(d));
    r = r * fmaf(-d, r, 2.0f);
    r = r * fmaf(-d, r, 2.0f);
    r = r * fmaf(-d, r, 2.0f);
    return r;
}
__device__ __forceinline__ float sig_fast(float x) {
    return rcp_fast(1.0f + exp_fast(-x));
}
__device__ __forceinline__ float tanh_fast(float x) {
    float a = fabsf(x);
    float t = exp_fast(-2.0f * a);
    float r = (1.0f - t) * rcp_fast(1.0f + t);
    return copysignf(r, x);
}
__device__ __forceinline__ float to_tf32(float x) {
    float y; asm("cvt.rna.tf32.f32 %0, %1;" : "=f"(y) : "f"(x)); return y;
}

// ---------------- tf32 pre-rounding pass ----------------
__global__ void round_tf32(const float* __restrict__ src, float* __restrict__ dst, int n4)
{
    int i = blockIdx.x * blockDim.x + threadIdx.x;
    int stride = gridDim.x * blockDim.x;
    for (; i < n4; i += stride) {
        float4 v = ((const float4*)src)[i];
        v.x = to_tf32(v.x); v.y = to_tf32(v.y);
        v.z = to_tf32(v.z); v.w = to_tf32(v.w);
        ((float4*)dst)[i] = v;
    }
}

// ================= TF32 MMA logits GEMM v2 =================
// Pre-rounded operands (no cvt in store path), single __syncthreads per k-chunk.
// C = remap( A[4096,512] @ B[20000,512]^T + bias ), row m=t*128+b -> out row b*TD+t
#define LST 136
__global__ __launch_bounds__(256) void gemm_tf32_logits(
    const float* __restrict__ A, const float* __restrict__ B,
    const float* __restrict__ bias, float* __restrict__ C)
{
    __shared__ float As[2][16][LST];
    __shared__ float Bs[2][16][LST];
    const int bm = blockIdx.y * 128;
    const int bn = blockIdx.x * 128;
    const int tid = threadIdx.x;
    const int warp = tid >> 5, lane = tid & 31;
    const int wm = (warp >> 2) * 64, wn = (warp & 3) * 32;
    const int g = lane >> 2, tg = lane & 3;

    const int lr = tid & 127;
    const int lc = tid >> 7;
    const float* Ap = A + (size_t)(bm + lr) * 512 + lc * 4;
    const int bnr = bn + lr;
    const bool bok = (bnr < VV);
    const float* Bp = B + (size_t)(bok ? bnr : 0) * 512 + lc * 4;

    float acc[4][4][4];
#pragma unroll
    for (int mt = 0; mt < 4; mt++)
#pragma unroll
        for (int nt = 0; nt < 4; nt++)
#pragma unroll
            for (int i = 0; i < 4; i++) acc[mt][nt][i] = 0.f;

    float4 av0 = *(const float4*)(Ap);
    float4 av1 = *(const float4*)(Ap + 8);
    float4 bv0 = bok ? *(const float4*)(Bp)     : make_float4(0.f,0.f,0.f,0.f);
    float4 bv1 = bok ? *(const float4*)(Bp + 8) : make_float4(0.f,0.f,0.f,0.f);

#define STORE_T(buf) do { \
    As[buf][lc*4+0][lr]=av0.x; As[buf][lc*4+1][lr]=av0.y; \
    As[buf][lc*4+2][lr]=av0.z; As[buf][lc*4+3][lr]=av0.w; \
    As[buf][lc*4+8][lr]=av1.x; As[buf][lc*4+9][lr]=av1.y; \
    As[buf][lc*4+10][lr]=av1.z; As[buf][lc*4+11][lr]=av1.w; \
    Bs[buf][lc*4+0][lr]=bv0.x; Bs[buf][lc*4+1][lr]=bv0.y; \
    Bs[buf][lc*4+2][lr]=bv0.z; Bs[buf][lc*4+3][lr]=bv0.w; \
    Bs[buf][lc*4+8][lr]=bv1.x; Bs[buf][lc*4+9][lr]=bv1.y; \
    Bs[buf][lc*4+10][lr]=bv1.z; Bs[buf][lc*4+11][lr]=bv1.w; \
} while(0)

    STORE_T(0);
    __syncthreads();

    for (int kb = 0; kb < 32; kb++) {
        const int cur = kb & 1;
        if (kb < 31) {
            const float* Ap2 = Ap + (kb + 1) * 16;
            const float* Bp2 = Bp + (kb + 1) * 16;
            av0 = *(const float4*)(Ap2);
            av1 = *(const float4*)(Ap2 + 8);
            bv0 = bok ? *(const float4*)(Bp2)     : make_float4(0.f,0.f,0.f,0.f);
            bv1 = bok ? *(const float4*)(Bp2 + 8) : make_float4(0.f,0.f,0.f,0.f);
        }
#pragma unroll
        for (int ks = 0; ks < 2; ks++) {
            const int k = ks * 8;
            unsigned afr[4][4], bfr[4][2];
#pragma unroll
            for (int mt = 0; mt < 4; mt++) {
                const int m = wm + mt * 16 + g;
                afr[mt][0] = __float_as_uint(As[cur][k + tg][m]);
                afr[mt][1] = __float_as_uint(As[cur][k + tg][m + 8]);
                afr[mt][2] = __float_as_uint(As[cur][k + tg + 4][m]);
                afr[mt][3] = __float_as_uint(As[cur][k + tg + 4][m + 8]);
            }
#pragma unroll
            for (int nt = 0; nt < 4; nt++) {
                const int n = wn + nt * 8 + g;
                bfr[nt][0] = __float_as_uint(Bs[cur][k + tg][n]);
                bfr[nt][1] = __float_as_uint(Bs[cur][k + tg + 4][n]);
            }
#pragma unroll
            for (int mt = 0; mt < 4; mt++)
#pragma unroll
                for (int nt = 0; nt < 4; nt++) {
                    asm volatile(
                        "mma.sync.aligned.m16n8k8.row.col.f32.tf32.tf32.f32 "
                        "{%0,%1,%2,%3}, {%4,%5,%6,%7}, {%8,%9}, {%0,%1,%2,%3};"
                        : "+f"(acc[mt][nt][0]), "+f"(acc[mt][nt][1]),
                          "+f"(acc[mt][nt][2]), "+f"(acc[mt][nt][3])
                        : "r"(afr[mt][0]), "r"(afr[mt][1]), "r"(afr[mt][2]), "r"(afr[mt][3]),
                          "r"(bfr[nt][0]), "r"(bfr[nt][1]));
                }
        }
        // store NEXT chunk into the other buffer: disjoint from current reads,
        // so a single barrier per iteration is sufficient.
        if (kb < 31) STORE_T(cur ^ 1);
        __syncthreads();
    }

#pragma unroll
    for (int mt = 0; mt < 4; mt++) {
        const int m0 = bm + wm + mt * 16 + g;
        const int r0 = (m0 & 127) * TD + (m0 >> 7);
        const int m1 = m0 + 8;
        const int r1 = (m1 & 127) * TD + (m1 >> 7);
#pragma unroll
        for (int nt = 0; nt < 4; nt++) {
            const int n0 = bn + wn + nt * 8 + 2 * tg;
            if (n0 < VV) {
                const float bv_0 = bias[n0], bv_1 = bias[n0 + 1];
                C[(size_t)r0 * VV + n0]     = acc[mt][nt][0] + bv_0;
                C[(size_t)r0 * VV + n0 + 1] = acc[mt][nt][1] + bv_1;
                C[(size_t)r1 * VV + n0]     = acc[mt][nt][2] + bv_0;
                C[(size_t)r1 * VV + n0 + 1] = acc[mt][nt][3] + bv_1;
            }
        }
    }
}

// ---------------- generic SGEMM-NT (R6) ----------------
__global__ __launch_bounds__(256) void gemm_nt(
    const float* __restrict__ A, int lda, const int* __restrict__ arow,
    const float* __restrict__ B, int ldb, const float* __restrict__ bias,
    float* __restrict__ C, int M, int N, int K, int mode)
{
    __shared__ float As[8][132];
    __shared__ float Bs[8][132];
    const int bn = blockIdx.x * 128;
    const int bm = blockIdx.y * 128;
    const int tid = threadIdx.x;
    const int lr = tid >> 1;
    const int lk = (tid & 1) << 2;
    const int tm = (tid >> 4) << 3;
    const int tn = (tid & 15) << 3;

    const int am = bm + lr;
    const int ar = arow ? arow[am] : am;
    const float* Ap = A + (size_t)ar * lda + lk;
    const int bnr = bn + lr;
    const bool bval = (bnr < N);
    const float* Bp = B + (size_t)(bval ? bnr : 0) * ldb + lk;

    float acc[8][8];
#pragma unroll
    for (int i = 0; i < 8; i++)
#pragma unroll
        for (int j = 0; j < 8; j++) acc[i][j] = 0.f;

    for (int k0 = 0; k0 < K; k0 += 8) {
        float4 av = *(const float4*)(Ap + k0);
        float4 bv = bval ? *(const float4*)(Bp + k0) : make_float4(0.f, 0.f, 0.f, 0.f);
        __syncthreads();
        As[lk + 0][lr] = av.x; As[lk + 1][lr] = av.y; As[lk + 2][lr] = av.z; As[lk + 3][lr] = av.w;
        Bs[lk + 0][lr] = bv.x; Bs[lk + 1][lr] = bv.y; Bs[lk + 2][lr] = bv.z; Bs[lk + 3][lr] = bv.w;
        __syncthreads();
#pragma unroll
        for (int kk = 0; kk < 8; kk++) {
            float a[8], b[8];
            *(float4*)(a)     = *(const float4*)&As[kk][tm];
            *(float4*)(a + 4) = *(const float4*)&As[kk][tm + 4];
            *(float4*)(b)     = *(const float4*)&Bs[kk][tn];
            *(float4*)(b + 4) = *(const float4*)&Bs[kk][tn + 4];
#pragma unroll
            for (int i = 0; i < 8; i++)
#pragma unroll
                for (int j = 0; j < 8; j++)
                    acc[i][j] += a[i] * b[j];
        }
    }
#pragma unroll
    for (int i = 0; i < 8; i++) {
        const int m = bm + tm + i;
#pragma unroll
        for (int j = 0; j < 8; j++) {
            const int n = bn + tn + j;
            if (n < N) {
                float v = acc[i][j] + (bias ? bias[n] : 0.f);
                C[(size_t)m * N + n] = v;
            }
        }
    }
}

// ---------------- encoder step: split-K over 2 blocks (R6, validated) ----------------
__global__ __launch_bounds__(256) void enc_step(const float* __restrict__ Whh, int t)
{
    __shared__ float hs[32][34];
    __shared__ float ws[4][32][34];
    __shared__ unsigned s_old;
    const int tid = threadIdx.x;
    const int tj = tid & 15;
    const int tb = tid >> 4;
    const int j0 = blockIdx.x * 32;
    const int b0 = blockIdx.y * 32;
    const int kz = blockIdx.z;
    const int tile = blockIdx.y * 16 + blockIdx.x;
    const float* hin = (t & 1) ? g_h1 : g_h0;
    float* hout      = (t & 1) ? g_h0 : g_h1;

    float acc[4][2][2];
#pragma unroll
    for (int g = 0; g < 4; g++) { acc[g][0][0] = acc[g][0][1] = acc[g][1][0] = acc[g][1][1] = 0.f; }

    for (int c = 0; c < 8; c++) {
        const int k0 = kz * 256 + c * 32;
        __syncthreads();
#pragma unroll
        for (int i = 0; i < 4; i++) {
            int idx = i * 256 + tid;
            int bb = idx >> 5, kk = idx & 31;
            hs[kk][bb] = hin[(size_t)(b0 + bb) * 512 + k0 + kk];
        }
#pragma unroll
        for (int i = 0; i < 16; i++) {
            int idx = i * 256 + tid;
            int g = idx >> 10, jj = (idx >> 5) & 31, kk = idx & 31;
            ws[g][kk][jj] = Whh[(size_t)((g << 9) + j0 + jj) * 512 + k0 + kk];
        }
        __syncthreads();
#pragma unroll
        for (int kk = 0; kk < 32; kk++) {
            float2 hp = *(const float2*)&hs[kk][tb * 2];
#pragma unroll
            for (int g = 0; g < 4; g++) {
                float2 wp = *(const float2*)&ws[g][kk][tj * 2];
                acc[g][0][0] += hp.x * wp.x;
                acc[g][0][1] += hp.x * wp.y;
                acc[g][1][0] += hp.y * wp.x;
                acc[g][1][1] += hp.y * wp.y;
            }
        }
    }

    float* myp = g_part + ((size_t)kz * 64 + tile) * 4096 + tid * 16;
#pragma unroll
    for (int g = 0; g < 4; g++)
#pragma unroll
        for (int bi = 0; bi < 2; bi++)
#pragma unroll
            for (int ji = 0; ji < 2; ji++)
                myp[g * 4 + bi * 2 + ji] = acc[g][bi][ji];
    __threadfence();
    __syncthreads();
    if (tid == 0) s_old = atomicAdd(&g_ctr[tile], 1u);
    __syncthreads();
    if (s_old == 0) return;

    const float* op = g_part + ((size_t)(1 - kz) * 64 + tile) * 4096 + tid * 16;
#pragma unroll
    for (int bi = 0; bi < 2; bi++)
#pragma unroll
        for (int ji = 0; ji < 2; ji++) {
            const int b = b0 + tb * 2 + bi;
            const int j = j0 + tj * 2 + ji;
            const size_t xb = ((size_t)b * SS + t) * 2048 + j;
            float ig = acc[0][bi][ji] + __ldcg(&op[0  + bi * 2 + ji]) + g_xg[xb];
            float fg = acc[1][bi][ji] + __ldcg(&op[4  + bi * 2 + ji]) + g_xg[xb + 512];
            float gg = acc[2][bi][ji] + __ldcg(&op[8  + bi * 2 + ji]) + g_xg[xb + 1024];
            float og = acc[3][bi][ji] + __ldcg(&op[12 + bi * 2 + ji]) + g_xg[xb + 1536];
            float cp = g_c[b * 512 + j];
            float cn = sig_fast(fg) * cp + sig_fast(ig) * tanh_fast(gg);
            float hn = sig_fast(og) * tanh_fast(cn);
            g_c[b * 512 + j] = cn;
            hout[b * 512 + j] = hn;
            g_enc_out[((size_t)b * SS + t) * 512 + j] = hn;
        }
    if (tid == 0) atomicExch(&g_ctr[tile], 0u);
}

// ---------------- decoder step: split kz=0 -> ctx@dWih, kz=1 -> h@dWhh (R6) ----------------
__global__ __launch_bounds__(256) void dec_step(const float* __restrict__ dWih,
                                                const float* __restrict__ dWhh, int t)
{
    __shared__ float hs[32][34];
    __shared__ float ws[4][32][34];
    __shared__ unsigned s_old;
    const int tid = threadIdx.x;
    const int tj = tid & 15;
    const int tb = tid >> 4;
    const int j0 = blockIdx.x * 32;
    const int b0 = blockIdx.y * 32;
    const int kz = blockIdx.z;
    const int tile = blockIdx.y * 16 + blockIdx.x;
    const float* hin = (t & 1) ? g_h1 : g_h0;
    float* hout      = (t & 1) ? g_h0 : g_h1;
    const float* src = kz ? hin : g_ctx;

    float acc[4][2][2];
#pragma unroll
    for (int g = 0; g < 4; g++) { acc[g][0][0] = acc[g][0][1] = acc[g][1][0] = acc[g][1][1] = 0.f; }

    for (int c = 0; c < 16; c++) {
        const int k0 = c * 32;
        __syncthreads();
#pragma unroll
        for (int i = 0; i < 4; i++) {
            int idx = i * 256 + tid;
            int bb = idx >> 5, kk = idx & 31;
            hs[kk][bb] = src[(size_t)(b0 + bb) * 512 + k0 + kk];
        }
#pragma unroll
        for (int i = 0; i < 16; i++) {
            int idx = i * 256 + tid;
            int g = idx >> 10, jj = (idx >> 5) & 31, kk = idx & 31;
            int n = (g << 9) + j0 + jj;
            ws[g][kk][jj] = kz ? dWhh[(size_t)n * 512 + k0 + kk]
                               : dWih[(size_t)n * 768 + 256 + k0 + kk];
        }
        __syncthreads();
#pragma unroll
        for (int kk = 0; kk < 32; kk++) {
            float2 hp = *(const float2*)&hs[kk][tb * 2];
#pragma unroll
            for (int g = 0; g < 4; g++) {
                float2 wp = *(const float2*)&ws[g][kk][tj * 2];
                acc[g][0][0] += hp.x * wp.x;
                acc[g][0][1] += hp.x * wp.y;
                acc[g][1][0] += hp.y * wp.x;
                acc[g][1][1] += hp.y * wp.y;
            }
        }
    }

    float* myp = g_part + ((size_t)kz * 64 + tile) * 4096 + tid * 16;
#pragma unroll
    for (int g = 0; g < 4; g++)
#pragma unroll
        for (int bi = 0; bi < 2; bi++)
#pragma unroll
            for (int ji = 0; ji < 2; ji++)
                myp[g * 4 + bi * 2 + ji] = acc[g][bi][ji];
    __threadfence();
    __syncthreads();
    if (tid == 0) s_old = atomicAdd(&g_ctr[tile], 1u);
    __syncthreads();
    if (s_old == 0) return;

    const float* op = g_part + ((size_t)(1 - kz) * 64 + tile) * 4096 + tid * 16;
#pragma unroll
    for (int bi = 0; bi < 2; bi++)
#pragma unroll
        for (int ji = 0; ji < 2; ji++) {
            const int b = b0 + tb * 2 + bi;
            const int j = j0 + tj * 2 + ji;
            const size_t mb = ((size_t)t * BB + b) * 2048 + j;
            float ig = acc[0][bi][ji] + __ldcg(&op[0  + bi * 2 + ji]) + g_embW[mb];
            float fg = acc[1][bi][ji] + __ldcg(&op[4  + bi * 2 + ji]) + g_embW[mb + 512];
            float gg = acc[2][bi][ji] + __ldcg(&op[8  + bi * 2 + ji]) + g_embW[mb + 1024];
            float og = acc[3][bi][ji] + __ldcg(&op[12 + bi * 2 + ji]) + g_embW[mb + 1536];
            float cp = g_c[b * 512 + j];
            float cn = sig_fast(fg) * cp + sig_fast(ig) * tanh_fast(gg);
            float hn = sig_fast(og) * tanh_fast(cn);
            g_c[b * 512 + j] = cn;
            hout[b * 512 + j] = hn;
            g_hs[((size_t)t * BB + b) * 512 + j] = hn;
        }
    if (tid == 0) atomicExch(&g_ctr[tile], 0u);
}

// ---------------- q = h@Wq.T + bq (R6) ----------------
__global__ __launch_bounds__(256) void q_step(const float* __restrict__ Wq,
                                              const float* __restrict__ bq, int t)
{
    __shared__ float hs[32][34];
    __shared__ float ws[32][34];
    const int tid = threadIdx.x;
    const int tj = tid & 15;
    const int tb = tid >> 4;
    const int j0 = blockIdx.x * 32;
    const int b0 = blockIdx.y * 32;
    const float* hin = (t & 1) ? g_h1 : g_h0;

    float acc[2][2] = {{0.f, 0.f}, {0.f, 0.f}};
    for (int k0 = 0; k0 < 512; k0 += 32) {
        __syncthreads();
#pragma unroll
        for (int i = 0; i < 4; i++) {
            int idx = i * 256 + tid;
            int bb = idx >> 5, kk = idx & 31;
            hs[kk][bb] = hin[(size_t)(b0 + bb) * 512 + k0 + kk];
        }
#pragma unroll
        for (int i = 0; i < 4; i++) {
            int idx = i * 256 + tid;
            int jj = idx >> 5, kk = idx & 31;
            ws[kk][jj] = Wq[(size_t)(j0 + jj) * 512 + k0 + kk];
        }
        __syncthreads();
#pragma unroll
        for (int kk = 0; kk < 32; kk++) {
            float2 hp = *(const float2*)&hs[kk][tb * 2];
            float2 wp = *(const float2*)&ws[kk][tj * 2];
            acc[0][0] += hp.x * wp.x;
            acc[0][1] += hp.x * wp.y;
            acc[1][0] += hp.y * wp.x;
            acc[1][1] += hp.y * wp.y;
        }
    }
#pragma unroll
    for (int bi = 0; bi < 2; bi++)
#pragma unroll
        for (int ji = 0; ji < 2; ji++) {
            const int b = b0 + tb * 2 + bi;
            const int j = j0 + tj * 2 + ji;
            g_q[b * 512 + j] = acc[bi][ji] + bq[j];
        }
}

// ---------------- attention (R6) ----------------
__global__ __launch_bounds__(256) void att_step(const float* __restrict__ v_w,
                                                const float* __restrict__ v_b,
                                                const int* __restrict__ src,
                                                float* __restrict__ attn_out,
                                                int t, int writeAttn)
{
    const int b = blockIdx.x;
    const int tid = threadIdx.x;
    __shared__ float qs[512], vs[512], sc[64];
    qs[tid] = g_q[b * 512 + tid];
    qs[tid + 256] = g_q[b * 512 + tid + 256];
    vs[tid] = v_w[tid];
    vs[tid + 256] = v_w[tid + 256];
    __syncthreads();
    const int warp = tid >> 5, lane = tid & 31;
    for (int s = warp; s < 64; s += 8) {
        const float* kp = g_keys + ((size_t)b * SS + s) * 512;
        float sum = 0.f;
#pragma unroll 4
        for (int j = lane; j < 512; j += 32)
            sum += tanh_fast(qs[j] + kp[j]) * vs[j];
#pragma unroll
        for (int o = 16; o; o >>= 1) sum += __shfl_xor_sync(0xffffffffu, sum, o);
        if (lane == 0) {
            sum += v_b[0];
            if (src[b * SS + s] == 0) sum = -1e9f;
            sc[s] = sum;
        }
    }
    __syncthreads();
    if (warp == 0) {
        float a0 = sc[lane], a1 = sc[lane + 32];
        float m = fmaxf(a0, a1);
#pragma unroll
        for (int o = 16; o; o >>= 1) m = fmaxf(m, __shfl_xor_sync(0xffffffffu, m, o));
        float e0 = exp_fast(a0 - m), e1 = exp_fast(a1 - m);
        float ss = e0 + e1;
#pragma unroll
        for (int o = 16; o; o >>= 1) ss += __shfl_xor_sync(0xffffffffu, ss, o);
        float inv = rcp_fast(ss);
        sc[lane] = e0 * inv;
        sc[lane + 32] = e1 * inv;
        if (writeAttn) {
            attn_out[((size_t)b * TD + t) * SS + lane] = e0 * inv;
            attn_out[((size_t)b * TD + t) * SS + lane + 32] = e1 * inv;
        }
    }
    __syncthreads();
    for (int j = tid; j < 512; j += 256) {
        float a = 0.f;
        const float* ep = g_enc_out + (size_t)b * SS * 512 + j;
#pragma unroll 8
        for (int s = 0; s < 64; s++) a += sc[s] * ep[(size_t)s * 512];
        g_ctx[b * 512 + j] = a;
    }
}

// ---------------- small helpers ----------------
__global__ void zero_hc()
{
    int i = blockIdx.x * 256 + threadIdx.x;
    g_h0[i] = 0.f;
    g_c[i] = 0.f;
    if (i < 64) g_ctr[i] = 0u;
}

__global__ void build_rows(const int* __restrict__ tgt)
{
    int i = blockIdx.x * 256 + threadIdx.x;
    if (i < TD * BB) {
        int tt = i >> 7, b = i & 127;
        g_rows[i] = (tt == 0) ? 1 : tgt[b * 33 + tt];
    }
}

// ---------------- launch ----------------
extern "C" void kernel_launch(void* const* d_in, const int* in_sizes, int n_in,
                              void* d_out, int out_size)
{
    (void)in_sizes; (void)n_in;
    const int*   src     = (const int*)d_in[0];
    const int*   tgt     = (const int*)d_in[1];
    const float* enc_emb = (const float*)d_in[2];
    const float* enc_Wih = (const float*)d_in[3];
    const float* enc_Whh = (const float*)d_in[4];
    const float* enc_b   = (const float*)d_in[5];
    const float* dec_emb = (const float*)d_in[6];
    const float* Wq      = (const float*)d_in[7];
    const float* bq      = (const float*)d_in[8];
    const float* Wk      = (const float*)d_in[9];
    const float* bk      = (const float*)d_in[10];
    const float* v_w     = (const float*)d_in[11];
    const float* v_b     = (const float*)d_in[12];
    const float* dWih    = (const float*)d_in[13];
    const float* dWhh    = (const float*)d_in[14];
    const float* db      = (const float*)d_in[15];
    const float* Wo      = (const float*)d_in[16];
    const float* bo      = (const float*)d_in[17];
    float* out = (float*)d_out;

    void *p_xg, *p_enc, *p_keys, *p_embW, *p_hs, *p_rows, *p_wor, *p_hsr;
    cudaGetSymbolAddress(&p_xg,   g_xg);
    cudaGetSymbolAddress(&p_enc,  g_enc_out);
    cudaGetSymbolAddress(&p_keys, g_keys);
    cudaGetSymbolAddress(&p_embW, g_embW);
    cudaGetSymbolAddress(&p_hs,   g_hs);
    cudaGetSymbolAddress(&p_rows, g_rows);
    cudaGetSymbolAddress(&p_wor,  g_wor);
    cudaGetSymbolAddress(&p_hsr,  g_hsr);

    zero_hc<<<256, 256>>>();

    // pre-round Wo to tf32 (independent; 10.24M elems)
    round_tf32<<<2048, 256>>>(Wo, (float*)p_wor, VV * HH / 4);

    gemm_nt<<<dim3(16, 64), 256>>>(enc_emb, 256, src, enc_Wih, 256, enc_b,
                                   (float*)p_xg, 8192, 2048, 256, 0);
    build_rows<<<16, 256>>>(tgt);
    gemm_nt<<<dim3(16, 32), 256>>>(dec_emb, 256, (const int*)p_rows, dWih, 768, db,
                                   (float*)p_embW, 4096, 2048, 256, 0);

    for (int t = 0; t < SS; t++)
        enc_step<<<dim3(16, 4, 2), 256>>>(enc_Whh, t);

    gemm_nt<<<dim3(4, 64), 256>>>((const float*)p_enc, 512, nullptr, Wk, 512, bk,
                                  (float*)p_keys, 8192, 512, 512, 0);

    const long long LOGITS = (long long)BB * TD * VV;
    const long long TOTAL  = LOGITS + (long long)BB * TD * SS;
    int writeAttn = ((long long)out_size >= TOTAL);
    float* attn = out + LOGITS;

    for (int t = 0; t < TD; t++) {
        q_step<<<dim3(16, 4), 256>>>(Wq, bq, t);
        att_step<<<128, 256>>>(v_w, v_b, src, attn, t, writeAttn);
        dec_step<<<dim3(16, 4, 2), 256>>>(dWih, dWhh, t);
    }

    // pre-round hs, then logits on tensor cores with pre-rounded operands
    round_tf32<<<512, 256>>>((const float*)p_hs, (float*)p_hsr, TD * BB * HH / 4);
    gemm_tf32_logits<<<dim3(157, 32), 256>>>((const float*)p_hsr, (const float*)p_wor, bo, out);
}